// round 3
// baseline (speedup 1.0000x reference)
#include <cuda_runtime.h>
#include <math.h>

#define SLEN  2048
#define DIMC  1024
#define NH    16
#define HDIM  64
#define BATCH 2
#define MROWS (BATCH*SLEN)   /* 4096 */
#define IOS   1008           /* DIM - 16 */

// ---- scratch (allocation-free rule: __device__ globals) ----
__device__ float g_q [(size_t)MROWS * DIMC];
__device__ float g_k [(size_t)MROWS * DIMC];
__device__ float g_v [(size_t)MROWS * DIMC];
__device__ float g_ao[(size_t)MROWS * DIMC];

__device__ __forceinline__ void unpack4(const float4 v, float* a) {
    a[0] = v.x; a[1] = v.y; a[2] = v.z; a[3] = v.w;
}

// ============================================================
// GEMM C[M,N] = A[M,K] @ W[K,N], all dims 1024-wide row-major,
// M=4096. Tiles 64x64, 256 threads, 4x4 per thread, K-step 16.
// ============================================================
__global__ __launch_bounds__(256) void gemm_qkv(
    const float* __restrict__ A, const float* __restrict__ W,
    float* __restrict__ C)
{
    __shared__ float sAT[16][68];   // [kk][m-row], transposed for float4 frags
    __shared__ float sB [16][68];   // [kk][n-col]
    const int tx = threadIdx.x, ty = threadIdx.y;
    const int tid = ty * 16 + tx;
    const int m0 = blockIdx.y * 64, n0 = blockIdx.x * 64;
    const int ra  = tid >> 2,  kqa = (tid & 3)  * 4;
    const int kkb = tid >> 4,  nqb = (tid & 15) * 4;
    const float* Ap = A + (size_t)(m0 + ra) * DIMC + kqa;
    const float* Bp = W + (size_t)kkb * DIMC + n0 + nqb;

    float acc[4][4] = {};
    for (int k0 = 0; k0 < DIMC; k0 += 16) {
        float4 av = *(const float4*)(Ap + k0);
        float4 bv = *(const float4*)(Bp + (size_t)k0 * DIMC);
        sAT[kqa + 0][ra] = av.x; sAT[kqa + 1][ra] = av.y;
        sAT[kqa + 2][ra] = av.z; sAT[kqa + 3][ra] = av.w;
        *(float4*)&sB[kkb][nqb] = bv;
        __syncthreads();
        #pragma unroll
        for (int kk = 0; kk < 16; kk++) {
            float a[4], b[4];
            unpack4(*(const float4*)&sAT[kk][ty * 4], a);
            unpack4(*(const float4*)&sB [kk][tx * 4], b);
            #pragma unroll
            for (int ii = 0; ii < 4; ii++)
                #pragma unroll
                for (int jj = 0; jj < 4; jj++)
                    acc[ii][jj] += a[ii] * b[jj];
        }
        __syncthreads();
    }
    #pragma unroll
    for (int ii = 0; ii < 4; ii++) {
        float4 o = make_float4(acc[ii][0], acc[ii][1], acc[ii][2], acc[ii][3]);
        *(float4*)&C[(size_t)(m0 + ty * 4 + ii) * DIMC + n0 + tx * 4] = o;
    }
}

// ============================================================
// Output projection + residual + IO epilogue:
// out = x + AO @ wo ; out[:,1009]+=getc ; out[:,1011]+=putc ; out[:,1021]=putc
// ============================================================
__global__ __launch_bounds__(256) void gemm_out(
    const float* __restrict__ A, const float* __restrict__ W,
    float* __restrict__ C, const float* __restrict__ resid,
    const float* __restrict__ getc, const float* __restrict__ putc)
{
    __shared__ float sAT[16][68];
    __shared__ float sB [16][68];
    const int tx = threadIdx.x, ty = threadIdx.y;
    const int tid = ty * 16 + tx;
    const int m0 = blockIdx.y * 64, n0 = blockIdx.x * 64;
    const int ra  = tid >> 2,  kqa = (tid & 3)  * 4;
    const int kkb = tid >> 4,  nqb = (tid & 15) * 4;
    const float* Ap = A + (size_t)(m0 + ra) * DIMC + kqa;
    const float* Bp = W + (size_t)kkb * DIMC + n0 + nqb;

    float acc[4][4] = {};
    for (int k0 = 0; k0 < DIMC; k0 += 16) {
        float4 av = *(const float4*)(Ap + k0);
        float4 bv = *(const float4*)(Bp + (size_t)k0 * DIMC);
        sAT[kqa + 0][ra] = av.x; sAT[kqa + 1][ra] = av.y;
        sAT[kqa + 2][ra] = av.z; sAT[kqa + 3][ra] = av.w;
        *(float4*)&sB[kkb][nqb] = bv;
        __syncthreads();
        #pragma unroll
        for (int kk = 0; kk < 16; kk++) {
            float a[4], b[4];
            unpack4(*(const float4*)&sAT[kk][ty * 4], a);
            unpack4(*(const float4*)&sB [kk][tx * 4], b);
            #pragma unroll
            for (int ii = 0; ii < 4; ii++)
                #pragma unroll
                for (int jj = 0; jj < 4; jj++)
                    acc[ii][jj] += a[ii] * b[jj];
        }
        __syncthreads();
    }
    #pragma unroll
    for (int ii = 0; ii < 4; ii++) {
        const int m = m0 + ty * 4 + ii;
        const int nb = n0 + tx * 4;
        float v[4];
        #pragma unroll
        for (int jj = 0; jj < 4; jj++) {
            const int n = nb + jj;
            float val = acc[ii][jj] + resid[(size_t)m * DIMC + n];
            if (n == IOS + 1)  val += getc[m];
            if (n == IOS + 3)  val += putc[m];
            if (n == IOS + 13) val  = putc[m];
            v[jj] = val;
        }
        *(float4*)&C[(size_t)m * DIMC + nb] = make_float4(v[0], v[1], v[2], v[3]);
    }
}

// ============================================================
// Flash-style attention with ALiBi + causal + head-0 getchar
// read-bias override. Block = (16,16) over one (64 q-rows, h, b)
// tile; online softmax, 16-lane shuffle row reductions.
// Each 64x64 tile = 1024 float4 slots -> 4 slots per thread.
// ============================================================
#define ATTN_SMEM (3 * 64 * 68 * 4)

__global__ __launch_bounds__(256) void attn_kernel(
    const float* __restrict__ q, const float* __restrict__ k,
    const float* __restrict__ v, const float* __restrict__ x,
    const float* __restrict__ getc, float* __restrict__ ao)
{
    extern __shared__ float sm[];
    float (*sQT)[68] = (float(*)[68])(sm);            // Q^T [d][i], pre-scaled
    float (*sKP)[68] = (float(*)[68])(sm + 64 * 68);  // K^T [d][j], then P [i][j]
    float (*sV )[68] = (float(*)[68])(sm + 2 * 64 * 68); // V [j][d]

    const int tx = threadIdx.x, ty = threadIdx.y;
    const int tid = ty * 16 + tx;
    const int it = blockIdx.x, h = blockIdx.y, b = blockIdx.z;
    const int i0 = it * 64;
    const size_t bS = (size_t)b * SLEN;

    // Per-thread tile-load coordinates: 4 slots covering 64 rows x 64 cols.
    int lrow[4], lcol[4];
    #pragma unroll
    for (int c = 0; c < 4; c++) {
        const int slot = tid + 256 * c;
        lrow[c] = slot >> 4;           // 0..63
        lcol[c] = (slot & 15) * 4;     // 0..60
    }

    // Load Q tile transposed, pre-scaled by 1/sqrt(hd) = 0.125
    #pragma unroll
    for (int c = 0; c < 4; c++) {
        float4 qv = *(const float4*)(q + (bS + i0 + lrow[c]) * DIMC + h * HDIM + lcol[c]);
        sQT[lcol[c] + 0][lrow[c]] = qv.x * 0.125f;
        sQT[lcol[c] + 1][lrow[c]] = qv.y * 0.125f;
        sQT[lcol[c] + 2][lrow[c]] = qv.z * 0.125f;
        sQT[lcol[c] + 3][lrow[c]] = qv.w * 0.125f;
    }

    const float slope = exp2f(-0.5f * (float)(h + 1));
    const bool h0 = (h == 0);

    float m_i[4], l_i[4], O[4][4];
    bool  gc[4];
    float tgt[4];
    #pragma unroll
    for (int ii = 0; ii < 4; ii++) {
        m_i[ii] = -INFINITY; l_i[ii] = 0.f;
        #pragma unroll
        for (int jj = 0; jj < 4; jj++) O[ii][jj] = 0.f;
        const int gi = i0 + ty * 4 + ii;
        gc[ii] = (getc[bS + gi] > 0.5f);
        const float* xr = x + (bS + gi) * DIMC + IOS;
        tgt[ii] = xr[0] + 1.0f + xr[1];
    }

    const int njt = h0 ? (SLEN / 64) : (it + 1);   // head 0 reads non-causally
    for (int jt = 0; jt < njt; jt++) {
        const int j0 = jt * 64;
        float4 kv[4], vv[4];
        #pragma unroll
        for (int c = 0; c < 4; c++) {
            kv[c] = *(const float4*)(k + (bS + j0 + lrow[c]) * DIMC + h * HDIM + lcol[c]);
            vv[c] = *(const float4*)(v + (bS + j0 + lrow[c]) * DIMC + h * HDIM + lcol[c]);
        }
        __syncthreads();   // prior tile's P/V reads done (also orders Q stores, iter 0)
        #pragma unroll
        for (int c = 0; c < 4; c++) {
            sKP[lcol[c] + 0][lrow[c]] = kv[c].x;
            sKP[lcol[c] + 1][lrow[c]] = kv[c].y;
            sKP[lcol[c] + 2][lrow[c]] = kv[c].z;
            sKP[lcol[c] + 3][lrow[c]] = kv[c].w;
            *(float4*)&sV[lrow[c]][lcol[c]] = vv[c];
        }
        __syncthreads();

        // GEMM1: scores = (Q*0.125) @ K^T  (4x4 per thread)
        float p[4][4] = {};
        #pragma unroll 16
        for (int d = 0; d < HDIM; d++) {
            float a[4], bb[4];
            unpack4(*(const float4*)&sQT[d][ty * 4], a);
            unpack4(*(const float4*)&sKP[d][tx * 4], bb);
            #pragma unroll
            for (int ii = 0; ii < 4; ii++)
                #pragma unroll
                for (int jj = 0; jj < 4; jj++)
                    p[ii][jj] += a[ii] * bb[jj];
        }

        // Bias + online softmax update
        #pragma unroll
        for (int ii = 0; ii < 4; ii++) {
            const int gi = i0 + ty * 4 + ii;
            #pragma unroll
            for (int jj = 0; jj < 4; jj++) {
                const int gj = j0 + tx * 4 + jj;
                float sv;
                if (h0 && gc[ii])
                    sv = -slope * fabsf(tgt[ii] - (float)gj);   // non-causal read bias
                else
                    sv = (gj <= gi) ? (p[ii][jj] - slope * (float)(gi - gj)) : -1e30f;
                p[ii][jj] = sv;
            }
            float tm = fmaxf(fmaxf(p[ii][0], p[ii][1]), fmaxf(p[ii][2], p[ii][3]));
            #pragma unroll
            for (int off = 8; off; off >>= 1)
                tm = fmaxf(tm, __shfl_xor_sync(0xffffffffu, tm, off, 16));
            const float mn = fmaxf(m_i[ii], tm);
            const float alpha = __expf(m_i[ii] - mn);   // 0 when m_i = -inf
            m_i[ii] = mn;
            float rs = 0.f;
            #pragma unroll
            for (int jj = 0; jj < 4; jj++) {
                float e = __expf(p[ii][jj] - mn);
                p[ii][jj] = e; rs += e;
            }
            #pragma unroll
            for (int off = 8; off; off >>= 1)
                rs += __shfl_xor_sync(0xffffffffu, rs, off, 16);
            l_i[ii] = l_i[ii] * alpha + rs;
            #pragma unroll
            for (int jj = 0; jj < 4; jj++) O[ii][jj] *= alpha;
        }

        __syncthreads();   // done reading sKP as K^T
        #pragma unroll
        for (int ii = 0; ii < 4; ii++)
            *(float4*)&sKP[ty * 4 + ii][tx * 4] =
                make_float4(p[ii][0], p[ii][1], p[ii][2], p[ii][3]);
        __syncthreads();

        // GEMM2: O += P @ V (P rows broadcast, V float4 frags)
        #pragma unroll 16
        for (int j = 0; j < 64; j++) {
            float bb[4];
            unpack4(*(const float4*)&sV[j][tx * 4], bb);
            #pragma unroll
            for (int ii = 0; ii < 4; ii++) {
                const float a = sKP[ty * 4 + ii][j];
                #pragma unroll
                for (int jj = 0; jj < 4; jj++)
                    O[ii][jj] += a * bb[jj];
            }
        }
    }

    #pragma unroll
    for (int ii = 0; ii < 4; ii++) {
        const float inv = 1.0f / l_i[ii];
        float4 o = make_float4(O[ii][0] * inv, O[ii][1] * inv,
                               O[ii][2] * inv, O[ii][3] * inv);
        *(float4*)&ao[(bS + i0 + ty * 4 + ii) * DIMC + h * HDIM + tx * 4] = o;
    }
}

// ============================================================
extern "C" void kernel_launch(void* const* d_in, const int* in_sizes, int n_in,
                              void* d_out, int out_size)
{
    const float* x   = (const float*)d_in[0];
    const float* gch = (const float*)d_in[1];
    const float* pch = (const float*)d_in[2];
    const float* wq  = (const float*)d_in[3];
    const float* wk  = (const float*)d_in[4];
    const float* wv  = (const float*)d_in[5];
    const float* wo  = (const float*)d_in[6];
    float* out = (float*)d_out;

    float *q, *k, *v, *ao;
    cudaGetSymbolAddress((void**)&q,  g_q);
    cudaGetSymbolAddress((void**)&k,  g_k);
    cudaGetSymbolAddress((void**)&v,  g_v);
    cudaGetSymbolAddress((void**)&ao, g_ao);

    dim3 blk(16, 16);
    dim3 gproj(DIMC / 64, MROWS / 64);

    gemm_qkv<<<gproj, blk>>>(x, wq, q);
    gemm_qkv<<<gproj, blk>>>(x, wk, k);
    gemm_qkv<<<gproj, blk>>>(x, wv, v);

    cudaFuncSetAttribute(attn_kernel,
                         cudaFuncAttributeMaxDynamicSharedMemorySize, ATTN_SMEM);
    attn_kernel<<<dim3(SLEN / 64, NH, BATCH), blk, ATTN_SMEM>>>(q, k, v, x, gch, ao);

    gemm_out<<<gproj, blk>>>(ao, wo, out, x, gch, pch);
}

// round 4
// speedup vs baseline: 2.6874x; 2.6874x over previous
#include <cuda_runtime.h>
#include <math.h>
#include <stdint.h>

#define SLEN  2048
#define DIMC  1024
#define NH    16
#define HDIM  64
#define BATCH 2
#define MROWS (BATCH*SLEN)   /* 4096 */
#define IOS   1008           /* DIM - 16 */

// ---- scratch (allocation-free rule: __device__ globals) ----
__device__ float g_q [(size_t)MROWS * DIMC];
__device__ float g_k [(size_t)MROWS * DIMC];
__device__ float g_v [(size_t)MROWS * DIMC];
__device__ float g_ao[(size_t)MROWS * DIMC];

__device__ __forceinline__ uint32_t f2tf(float f) {
    uint32_t u;
    asm("cvt.rna.tf32.f32 %0, %1;" : "=r"(u) : "f"(f));
    return u;
}

// D = A(16x8 tf32, row) * B(8x8 tf32, col) + D (fp32)
__device__ __forceinline__ void mma8(float c[4], const uint32_t a[4], const uint32_t b[2]) {
    asm volatile(
        "mma.sync.aligned.m16n8k8.row.col.f32.tf32.tf32.f32 "
        "{%0,%1,%2,%3}, {%4,%5,%6,%7}, {%8,%9}, {%0,%1,%2,%3};"
        : "+f"(c[0]), "+f"(c[1]), "+f"(c[2]), "+f"(c[3])
        : "r"(a[0]), "r"(a[1]), "r"(a[2]), "r"(a[3]), "r"(b[0]), "r"(b[1]));
}

// ============================================================
// tf32 tensor-core GEMM: C[M=4096,N=1024] = A @ W (+epilogue)
// block tile 128x128, 256 thr / 8 warps, warp tile 64x32,
// K-step 16, double-buffered smem.
// A smem stride 20 (banks 4g+tg), B smem stride 136 (8tg+g).
// ============================================================
#define GAS 20
#define GBS 136

__global__ __launch_bounds__(256, 2) void gemm_mma(
    const float* __restrict__ A, const float* __restrict__ W,
    float* __restrict__ C, const float* __restrict__ resid,
    const float* __restrict__ getc, const float* __restrict__ putc)
{
    __shared__ uint32_t sA[2][128 * GAS];
    __shared__ uint32_t sB[2][16 * GBS];

    const int tid = threadIdx.x, lane = tid & 31, w = tid >> 5;
    const int g = lane >> 2, tg = lane & 3;
    const int wm = w >> 2, wn = w & 3;              // warp tile origin (wm*64, wn*32)
    const int m0 = blockIdx.y * 128, n0 = blockIdx.x * 128;

    // global->smem load coords
    const int ar = tid >> 2, ac = (tid & 3) * 4;    // A: rows ar, ar+64
    const int br = tid >> 5, bc = (tid & 31) * 4;   // B: rows br, br+8

    float acc[16][4];
    #pragma unroll
    for (int i = 0; i < 16; i++)
        #pragma unroll
        for (int j = 0; j < 4; j++) acc[i][j] = 0.f;

    float4 pa[2], pb[2];
    // prologue: tile 0 -> buf 0
    #pragma unroll
    for (int i = 0; i < 2; i++) {
        pa[i] = *(const float4*)&A[(size_t)(m0 + ar + 64 * i) * DIMC + ac];
        pb[i] = *(const float4*)&W[(size_t)(br + 8 * i) * DIMC + n0 + bc];
    }
    #pragma unroll
    for (int i = 0; i < 2; i++) {
        uint32_t* d = &sA[0][(ar + 64 * i) * GAS + ac];
        d[0] = f2tf(pa[i].x); d[1] = f2tf(pa[i].y); d[2] = f2tf(pa[i].z); d[3] = f2tf(pa[i].w);
        uint32_t* e = &sB[0][(br + 8 * i) * GBS + bc];
        e[0] = f2tf(pb[i].x); e[1] = f2tf(pb[i].y); e[2] = f2tf(pb[i].z); e[3] = f2tf(pb[i].w);
    }
    __syncthreads();

    for (int kt = 0; kt < DIMC / 16; kt++) {
        const int buf = kt & 1, nxt = buf ^ 1;
        if (kt < DIMC / 16 - 1) {
            const int k0 = (kt + 1) * 16;
            #pragma unroll
            for (int i = 0; i < 2; i++) {
                pa[i] = *(const float4*)&A[(size_t)(m0 + ar + 64 * i) * DIMC + k0 + ac];
                pb[i] = *(const float4*)&W[(size_t)(k0 + br + 8 * i) * DIMC + n0 + bc];
            }
        }
        #pragma unroll
        for (int ks = 0; ks < 16; ks += 8) {
            uint32_t af[4][4], bf[4][2];
            #pragma unroll
            for (int ma = 0; ma < 4; ma++) {
                const int r = wm * 64 + ma * 16 + g;
                af[ma][0] = sA[buf][r * GAS + ks + tg];
                af[ma][1] = sA[buf][(r + 8) * GAS + ks + tg];
                af[ma][2] = sA[buf][r * GAS + ks + tg + 4];
                af[ma][3] = sA[buf][(r + 8) * GAS + ks + tg + 4];
            }
            #pragma unroll
            for (int na = 0; na < 4; na++) {
                const int c = wn * 32 + na * 8 + g;
                bf[na][0] = sB[buf][(ks + tg) * GBS + c];
                bf[na][1] = sB[buf][(ks + tg + 4) * GBS + c];
            }
            #pragma unroll
            for (int ma = 0; ma < 4; ma++)
                #pragma unroll
                for (int na = 0; na < 4; na++)
                    mma8(acc[ma * 4 + na], af[ma], bf[na]);
        }
        if (kt < DIMC / 16 - 1) {
            #pragma unroll
            for (int i = 0; i < 2; i++) {
                uint32_t* d = &sA[nxt][(ar + 64 * i) * GAS + ac];
                d[0] = f2tf(pa[i].x); d[1] = f2tf(pa[i].y); d[2] = f2tf(pa[i].z); d[3] = f2tf(pa[i].w);
                uint32_t* e = &sB[nxt][(br + 8 * i) * GBS + bc];
                e[0] = f2tf(pb[i].x); e[1] = f2tf(pb[i].y); e[2] = f2tf(pb[i].z); e[3] = f2tf(pb[i].w);
            }
            __syncthreads();
        }
    }

    // epilogue
    #pragma unroll
    for (int ma = 0; ma < 4; ma++) {
        #pragma unroll
        for (int na = 0; na < 4; na++) {
            const int rbase = m0 + wm * 64 + ma * 16 + g;
            const int cbase = n0 + wn * 32 + na * 8 + 2 * tg;
            #pragma unroll
            for (int half = 0; half < 2; half++) {
                const int m = rbase + 8 * half;
                float v0 = acc[ma * 4 + na][2 * half + 0];
                float v1 = acc[ma * 4 + na][2 * half + 1];
                if (resid) {
                    v0 += resid[(size_t)m * DIMC + cbase];
                    v1 += resid[(size_t)m * DIMC + cbase + 1];
                    #pragma unroll
                    for (int c = 0; c < 2; c++) {
                        const int n = cbase + c;
                        float* pv = c ? &v1 : &v0;
                        if (n == IOS + 1)  *pv += getc[m];
                        if (n == IOS + 3)  *pv += putc[m];
                        if (n == IOS + 13) *pv  = putc[m];
                    }
                }
                *(float2*)&C[(size_t)m * DIMC + cbase] = make_float2(v0, v1);
            }
        }
    }
}

// ============================================================
// Flash attention with tf32 tensor cores.
// 128 thr / 4 warps; warp owns 16 q-rows. j-tile 64, k(=d)=64.
// S = Q@K^T via mma (K tile is directly col-major B).
// softmax on C-frags; P -> smem (warp-private) -> A-frags; PV
// with V stored transposed. ALiBi + causal + head0 override.
// ============================================================
#define AS 68   /* smem row stride: 68 mod 32 = 4 -> banks 4g+tg */
#define ATTN_SMEM (4 * 64 * AS * 4)

__global__ __launch_bounds__(128) void attn_mma(
    const float* __restrict__ q, const float* __restrict__ k,
    const float* __restrict__ v, const float* __restrict__ x,
    const float* __restrict__ getc, float* __restrict__ ao)
{
    extern __shared__ uint32_t smem[];
    uint32_t* sQ  = smem;
    uint32_t* sK  = sQ  + 64 * AS;
    uint32_t* sVT = sK  + 64 * AS;
    uint32_t* sP  = sVT + 64 * AS;

    const int tid = threadIdx.x, lane = tid & 31, w = tid >> 5;
    const int g = lane >> 2, tg = lane & 3;
    const int it = blockIdx.x, h = blockIdx.y, b = blockIdx.z;
    const int i0 = it * 64;
    const size_t bS = (size_t)b * SLEN;

    // Load Q tile (scaled by exact 0.125), row-major [i][d]
    #pragma unroll
    for (int i = 0; i < 8; i++) {
        const int id = tid + 128 * i;
        const int row = id >> 4, col = (id & 15) * 4;
        float4 qv = *(const float4*)&q[(bS + i0 + row) * DIMC + h * HDIM + col];
        uint32_t* d = &sQ[row * AS + col];
        d[0] = f2tf(qv.x * 0.125f); d[1] = f2tf(qv.y * 0.125f);
        d[2] = f2tf(qv.z * 0.125f); d[3] = f2tf(qv.w * 0.125f);
    }

    const float slope = exp2f(-0.5f * (float)(h + 1));
    const bool h0 = (h == 0);

    // per-thread rows: r0 = i0 + w*16 + g, r1 = r0 + 8
    float m2[2] = {-INFINITY, -INFINITY}, l2[2] = {0.f, 0.f};
    float O[8][4];
    #pragma unroll
    for (int na = 0; na < 8; na++)
        #pragma unroll
        for (int j = 0; j < 4; j++) O[na][j] = 0.f;

    bool gcf[2]; float tgt[2];
    #pragma unroll
    for (int rs = 0; rs < 2; rs++) {
        const int gi = i0 + w * 16 + g + 8 * rs;
        gcf[rs] = (getc[bS + gi] > 0.5f) && h0;
        const float* xr = &x[(bS + gi) * DIMC + IOS];
        tgt[rs] = xr[0] + 1.0f + xr[1];
    }

    const int njt = h0 ? (SLEN / 64) : (it + 1);
    for (int jt = 0; jt < njt; jt++) {
        const int j0 = jt * 64;
        __syncthreads();   // previous tile's sK/sVT reads complete
        #pragma unroll
        for (int i = 0; i < 8; i++) {
            const int id = tid + 128 * i;
            const int row = id >> 4, col = (id & 15) * 4;
            float4 kv = *(const float4*)&k[(bS + j0 + row) * DIMC + h * HDIM + col];
            float4 vv = *(const float4*)&v[(bS + j0 + row) * DIMC + h * HDIM + col];
            uint32_t* d = &sK[row * AS + col];
            d[0] = f2tf(kv.x); d[1] = f2tf(kv.y); d[2] = f2tf(kv.z); d[3] = f2tf(kv.w);
            sVT[(col + 0) * AS + row] = f2tf(vv.x);
            sVT[(col + 1) * AS + row] = f2tf(vv.y);
            sVT[(col + 2) * AS + row] = f2tf(vv.z);
            sVT[(col + 3) * AS + row] = f2tf(vv.w);
        }
        __syncthreads();

        // GEMM1: S[16x64] = Q_w @ K^T
        float s[8][4];
        #pragma unroll
        for (int na = 0; na < 8; na++)
            #pragma unroll
            for (int j = 0; j < 4; j++) s[na][j] = 0.f;
        #pragma unroll
        for (int k8 = 0; k8 < 8; k8++) {
            uint32_t af[4];
            const int rb = (w * 16 + g) * AS + k8 * 8 + tg;
            af[0] = sQ[rb]; af[1] = sQ[rb + 8 * AS];
            af[2] = sQ[rb + 4]; af[3] = sQ[rb + 8 * AS + 4];
            #pragma unroll
            for (int na = 0; na < 8; na++) {
                uint32_t bf[2];
                const int nb = (na * 8 + g) * AS + k8 * 8 + tg;
                bf[0] = sK[nb]; bf[1] = sK[nb + 4];
                mma8(s[na], af, bf);
            }
        }

        // bias + online softmax per row-half
        #pragma unroll
        for (int rs = 0; rs < 2; rs++) {
            const int gi = i0 + w * 16 + g + 8 * rs;
            if (gcf[rs]) {
                #pragma unroll
                for (int na = 0; na < 8; na++)
                    #pragma unroll
                    for (int c = 0; c < 2; c++) {
                        const int gj = j0 + na * 8 + 2 * tg + c;
                        s[na][2 * rs + c] = -slope * fabsf(tgt[rs] - (float)gj);
                    }
            } else {
                #pragma unroll
                for (int na = 0; na < 8; na++)
                    #pragma unroll
                    for (int c = 0; c < 2; c++) {
                        const int gj = j0 + na * 8 + 2 * tg + c;
                        s[na][2 * rs + c] = (gj <= gi)
                            ? s[na][2 * rs + c] - slope * (float)(gi - gj) : -1e30f;
                    }
            }
            float tm = -INFINITY;
            #pragma unroll
            for (int na = 0; na < 8; na++)
                tm = fmaxf(tm, fmaxf(s[na][2 * rs], s[na][2 * rs + 1]));
            tm = fmaxf(tm, __shfl_xor_sync(0xffffffffu, tm, 1));
            tm = fmaxf(tm, __shfl_xor_sync(0xffffffffu, tm, 2));
            const float mn = fmaxf(m2[rs], tm);
            const float alpha = __expf(m2[rs] - mn);
            m2[rs] = mn;
            float rsum = 0.f;
            #pragma unroll
            for (int na = 0; na < 8; na++)
                #pragma unroll
                for (int c = 0; c < 2; c++) {
                    float e = __expf(s[na][2 * rs + c] - mn);
                    s[na][2 * rs + c] = e; rsum += e;
                }
            rsum += __shfl_xor_sync(0xffffffffu, rsum, 1);
            rsum += __shfl_xor_sync(0xffffffffu, rsum, 2);
            l2[rs] = l2[rs] * alpha + rsum;
            #pragma unroll
            for (int na = 0; na < 8; na++) {
                O[na][2 * rs + 0] *= alpha;
                O[na][2 * rs + 1] *= alpha;
            }
        }

        // P -> smem (warp-private rows), re-fragment as A
        #pragma unroll
        for (int na = 0; na < 8; na++) {
            const int r = w * 16 + g, c = na * 8 + 2 * tg;
            sP[r * AS + c]           = f2tf(s[na][0]);
            sP[r * AS + c + 1]       = f2tf(s[na][1]);
            sP[(r + 8) * AS + c]     = f2tf(s[na][2]);
            sP[(r + 8) * AS + c + 1] = f2tf(s[na][3]);
        }
        __syncwarp();

        // GEMM2: O += P @ V  (V^T as col-major B)
        #pragma unroll
        for (int k8 = 0; k8 < 8; k8++) {
            uint32_t af[4];
            const int rb = (w * 16 + g) * AS + k8 * 8 + tg;
            af[0] = sP[rb]; af[1] = sP[rb + 8 * AS];
            af[2] = sP[rb + 4]; af[3] = sP[rb + 8 * AS + 4];
            #pragma unroll
            for (int na = 0; na < 8; na++) {
                uint32_t bf[2];
                const int nb = (na * 8 + g) * AS + k8 * 8 + tg;
                bf[0] = sVT[nb]; bf[1] = sVT[nb + 4];
                mma8(O[na], af, bf);
            }
        }
    }

    // write out ao = O / l
    #pragma unroll
    for (int rs = 0; rs < 2; rs++) {
        const float inv = 1.0f / l2[rs];
        const size_t rowoff = (bS + i0 + w * 16 + g + 8 * rs) * DIMC + h * HDIM;
        #pragma unroll
        for (int na = 0; na < 8; na++) {
            *(float2*)&ao[rowoff + na * 8 + 2 * tg] =
                make_float2(O[na][2 * rs] * inv, O[na][2 * rs + 1] * inv);
        }
    }
}

// ============================================================
extern "C" void kernel_launch(void* const* d_in, const int* in_sizes, int n_in,
                              void* d_out, int out_size)
{
    const float* x   = (const float*)d_in[0];
    const float* gch = (const float*)d_in[1];
    const float* pch = (const float*)d_in[2];
    const float* wq  = (const float*)d_in[3];
    const float* wk  = (const float*)d_in[4];
    const float* wv  = (const float*)d_in[5];
    const float* wo  = (const float*)d_in[6];
    float* out = (float*)d_out;

    float *qp, *kp, *vp, *aop;
    cudaGetSymbolAddress((void**)&qp,  g_q);
    cudaGetSymbolAddress((void**)&kp,  g_k);
    cudaGetSymbolAddress((void**)&vp,  g_v);
    cudaGetSymbolAddress((void**)&aop, g_ao);

    dim3 gproj(DIMC / 128, MROWS / 128);
    gemm_mma<<<gproj, 256>>>(x, wq, qp, nullptr, nullptr, nullptr);
    gemm_mma<<<gproj, 256>>>(x, wk, kp, nullptr, nullptr, nullptr);
    gemm_mma<<<gproj, 256>>>(x, wv, vp, nullptr, nullptr, nullptr);

    cudaFuncSetAttribute(attn_mma,
                         cudaFuncAttributeMaxDynamicSharedMemorySize, ATTN_SMEM);
    attn_mma<<<dim3(SLEN / 64, NH, BATCH), 128, ATTN_SMEM>>>(qp, kp, vp, x, gch, aop);

    gemm_mma<<<gproj, 256>>>(aop, wo, out, x, gch, pch);
}

// round 5
// speedup vs baseline: 3.2259x; 1.2004x over previous
#include <cuda_runtime.h>
#include <math.h>
#include <stdint.h>

#define SLEN  2048
#define DIMC  1024
#define NH    16
#define HDIM  64
#define BATCH 2
#define MROWS (BATCH*SLEN)   /* 4096 */
#define IOS   1008           /* DIM - 16 */

// ---- scratch (allocation-free rule: __device__ globals) ----
__device__ float g_q [(size_t)MROWS * DIMC];
__device__ float g_k [(size_t)MROWS * DIMC];
__device__ float g_v [(size_t)MROWS * DIMC];
__device__ float g_ao[(size_t)MROWS * DIMC];

__device__ __forceinline__ uint32_t f2tf(float f) {
    uint32_t u;
    asm("cvt.rna.tf32.f32 %0, %1;" : "=r"(u) : "f"(f));
    return u;
}

// D = A(16x8 tf32, row) * B(8x8 tf32, col) + D (fp32)
__device__ __forceinline__ void mma8(float c[4], const uint32_t a[4], const uint32_t b[2]) {
    asm volatile(
        "mma.sync.aligned.m16n8k8.row.col.f32.tf32.tf32.f32 "
        "{%0,%1,%2,%3}, {%4,%5,%6,%7}, {%8,%9}, {%0,%1,%2,%3};"
        : "+f"(c[0]), "+f"(c[1]), "+f"(c[2]), "+f"(c[3])
        : "r"(a[0]), "r"(a[1]), "r"(a[2]), "r"(a[3]), "r"(b[0]), "r"(b[1]));
}

__device__ __forceinline__ void cpa16(uint32_t saddr, const void* gp) {
    asm volatile("cp.async.cg.shared.global [%0], [%1], 16;" :: "r"(saddr), "l"(gp));
}

// ============================================================
// tf32 tensor-core GEMM core: C[.,1024] = A[.,1024] @ W
// block tile 128x128, 256 thr / 8 warps, warp tile 64x32,
// K-step 16, double-buffered smem.
// ============================================================
#define GAS 20
#define GBS 136

__device__ __forceinline__ void gemm_body(
    const float* __restrict__ A, const float* __restrict__ W,
    float* __restrict__ C, const float* __restrict__ resid,
    const float* __restrict__ getc, const float* __restrict__ putc,
    bool cvt, float scale,
    uint32_t (*sA)[128 * GAS], uint32_t (*sB)[16 * GBS])
{
    const int tid = threadIdx.x, lane = tid & 31, w = tid >> 5;
    const int g = lane >> 2, tg = lane & 3;
    const int wm = w >> 2, wn = w & 3;
    const int m0 = blockIdx.y * 128, n0 = blockIdx.x * 128;

    const int ar = tid >> 2, ac = (tid & 3) * 4;
    const int br = tid >> 5, bc = (tid & 31) * 4;

    float acc[16][4];
    #pragma unroll
    for (int i = 0; i < 16; i++)
        #pragma unroll
        for (int j = 0; j < 4; j++) acc[i][j] = 0.f;

    float4 pa[2], pb[2];
    #pragma unroll
    for (int i = 0; i < 2; i++) {
        pa[i] = *(const float4*)&A[(size_t)(m0 + ar + 64 * i) * DIMC + ac];
        pb[i] = *(const float4*)&W[(size_t)(br + 8 * i) * DIMC + n0 + bc];
    }
    #pragma unroll
    for (int i = 0; i < 2; i++) {
        uint32_t* d = &sA[0][(ar + 64 * i) * GAS + ac];
        d[0] = f2tf(pa[i].x); d[1] = f2tf(pa[i].y); d[2] = f2tf(pa[i].z); d[3] = f2tf(pa[i].w);
        uint32_t* e = &sB[0][(br + 8 * i) * GBS + bc];
        e[0] = f2tf(pb[i].x); e[1] = f2tf(pb[i].y); e[2] = f2tf(pb[i].z); e[3] = f2tf(pb[i].w);
    }
    __syncthreads();

    for (int kt = 0; kt < DIMC / 16; kt++) {
        const int buf = kt & 1, nxt = buf ^ 1;
        if (kt < DIMC / 16 - 1) {
            const int k0 = (kt + 1) * 16;
            #pragma unroll
            for (int i = 0; i < 2; i++) {
                pa[i] = *(const float4*)&A[(size_t)(m0 + ar + 64 * i) * DIMC + k0 + ac];
                pb[i] = *(const float4*)&W[(size_t)(k0 + br + 8 * i) * DIMC + n0 + bc];
            }
        }
        #pragma unroll
        for (int ks = 0; ks < 16; ks += 8) {
            uint32_t af[4][4], bf[4][2];
            #pragma unroll
            for (int ma = 0; ma < 4; ma++) {
                const int r = wm * 64 + ma * 16 + g;
                af[ma][0] = sA[buf][r * GAS + ks + tg];
                af[ma][1] = sA[buf][(r + 8) * GAS + ks + tg];
                af[ma][2] = sA[buf][r * GAS + ks + tg + 4];
                af[ma][3] = sA[buf][(r + 8) * GAS + ks + tg + 4];
            }
            #pragma unroll
            for (int na = 0; na < 4; na++) {
                const int c = wn * 32 + na * 8 + g;
                bf[na][0] = sB[buf][(ks + tg) * GBS + c];
                bf[na][1] = sB[buf][(ks + tg + 4) * GBS + c];
            }
            #pragma unroll
            for (int ma = 0; ma < 4; ma++)
                #pragma unroll
                for (int na = 0; na < 4; na++)
                    mma8(acc[ma * 4 + na], af[ma], bf[na]);
        }
        if (kt < DIMC / 16 - 1) {
            #pragma unroll
            for (int i = 0; i < 2; i++) {
                uint32_t* d = &sA[nxt][(ar + 64 * i) * GAS + ac];
                d[0] = f2tf(pa[i].x); d[1] = f2tf(pa[i].y); d[2] = f2tf(pa[i].z); d[3] = f2tf(pa[i].w);
                uint32_t* e = &sB[nxt][(br + 8 * i) * GBS + bc];
                e[0] = f2tf(pb[i].x); e[1] = f2tf(pb[i].y); e[2] = f2tf(pb[i].z); e[3] = f2tf(pb[i].w);
            }
            __syncthreads();
        }
    }

    #pragma unroll
    for (int ma = 0; ma < 4; ma++) {
        #pragma unroll
        for (int na = 0; na < 4; na++) {
            const int rbase = m0 + wm * 64 + ma * 16 + g;
            const int cbase = n0 + wn * 32 + na * 8 + 2 * tg;
            #pragma unroll
            for (int half = 0; half < 2; half++) {
                const int m = rbase + 8 * half;
                float v0 = acc[ma * 4 + na][2 * half + 0];
                float v1 = acc[ma * 4 + na][2 * half + 1];
                if (cvt) {
                    v0 = __uint_as_float(f2tf(v0 * scale));
                    v1 = __uint_as_float(f2tf(v1 * scale));
                } else if (resid) {
                    v0 += resid[(size_t)m * DIMC + cbase];
                    v1 += resid[(size_t)m * DIMC + cbase + 1];
                    #pragma unroll
                    for (int c = 0; c < 2; c++) {
                        const int n = cbase + c;
                        float* pv = c ? &v1 : &v0;
                        if (n == IOS + 1)  *pv += getc[m];
                        if (n == IOS + 3)  *pv += putc[m];
                        if (n == IOS + 13) *pv  = putc[m];
                    }
                }
                *(float2*)&C[(size_t)m * DIMC + cbase] = make_float2(v0, v1);
            }
        }
    }
}

// Fused QKV: grid.z selects weight/output; Q pre-scaled by 0.125,
// all outputs written tf32-rounded (attn consumes them raw).
__global__ __launch_bounds__(256, 2) void gemm_qkv3(
    const float* __restrict__ x,
    const float* __restrict__ wq, const float* __restrict__ wk, const float* __restrict__ wv,
    float* __restrict__ q, float* __restrict__ k, float* __restrict__ v)
{
    __shared__ uint32_t sA[2][128 * GAS];
    __shared__ uint32_t sB[2][16 * GBS];
    const int z = blockIdx.z;
    const float* W = (z == 0) ? wq : (z == 1) ? wk : wv;
    float* C = (z == 0) ? q : (z == 1) ? k : v;
    const float scale = (z == 0) ? 0.125f : 1.0f;
    gemm_body(x, W, C, nullptr, nullptr, nullptr, true, scale, sA, sB);
}

// Output projection + residual + IO epilogue
__global__ __launch_bounds__(256, 2) void gemm_out(
    const float* __restrict__ A, const float* __restrict__ W,
    float* __restrict__ C, const float* __restrict__ resid,
    const float* __restrict__ getc, const float* __restrict__ putc)
{
    __shared__ uint32_t sA[2][128 * GAS];
    __shared__ uint32_t sB[2][16 * GBS];
    gemm_body(A, W, C, resid, getc, putc, false, 1.0f, sA, sB);
}

// ============================================================
// Flash attention, tf32 mma. 128 thr / 4 warps; warp = 16 q-rows.
// Inputs q,k,v already tf32-rounded (q pre-scaled). V row-major
// (B(k=j,n=d) = V[j][d], conflict-free). Q frags in registers;
// sQ smem reused as sP. cp.async tile loads. Heavy blocks first.
// ============================================================
#define AS 68   /* stride: banks 4g+tg conflict-free; 272B rows 16B-aligned */
#define ATTN_SMEM (3 * 64 * AS * 4)

__global__ __launch_bounds__(128, 3) void attn_mma(
    const float* __restrict__ q, const float* __restrict__ k,
    const float* __restrict__ v, const float* __restrict__ x,
    const float* __restrict__ getc, float* __restrict__ ao)
{
    extern __shared__ uint32_t smem[];
    uint32_t* sK  = smem;
    uint32_t* sV  = sK + 64 * AS;
    uint32_t* sQP = sV + 64 * AS;   // Q staging, then P

    const uint32_t sKa  = (uint32_t)__cvta_generic_to_shared(sK);
    const uint32_t sVa  = (uint32_t)__cvta_generic_to_shared(sV);
    const uint32_t sQPa = (uint32_t)__cvta_generic_to_shared(sQP);

    const int tid = threadIdx.x, lane = tid & 31, w = tid >> 5;
    const int g = lane >> 2, tg = lane & 3;
    const int it = gridDim.x - 1 - blockIdx.x;   // heavy blocks first
    const int h = blockIdx.y, b = blockIdx.z;
    const int i0 = it * 64;
    const size_t bS = (size_t)b * SLEN;

    // stage Q tile (already tf32+scaled) into sQP
    #pragma unroll
    for (int i = 0; i < 8; i++) {
        const int id = tid + 128 * i;
        const int row = id >> 4, col = (id & 15) * 4;
        cpa16(sQPa + (row * AS + col) * 4, &q[(bS + i0 + row) * DIMC + h * HDIM + col]);
    }
    asm volatile("cp.async.commit_group;\ncp.async.wait_group 0;" ::: "memory");
    __syncthreads();

    // hoist Q fragments into registers (loop-invariant A operand)
    uint32_t afq[8][4];
    #pragma unroll
    for (int k8 = 0; k8 < 8; k8++) {
        const int rb = (w * 16 + g) * AS + k8 * 8 + tg;
        afq[k8][0] = sQP[rb];          afq[k8][1] = sQP[rb + 8 * AS];
        afq[k8][2] = sQP[rb + 4];      afq[k8][3] = sQP[rb + 8 * AS + 4];
    }
    __syncthreads();   // all warps done with sQP before reuse as sP

    const float slope = exp2f(-0.5f * (float)(h + 1));
    const bool h0 = (h == 0);

    float m2[2] = {-INFINITY, -INFINITY}, l2[2] = {0.f, 0.f};
    float O[8][4];
    #pragma unroll
    for (int na = 0; na < 8; na++)
        #pragma unroll
        for (int j = 0; j < 4; j++) O[na][j] = 0.f;

    bool gcf[2]; float tgt[2];
    #pragma unroll
    for (int rs = 0; rs < 2; rs++) {
        const int gi = i0 + w * 16 + g + 8 * rs;
        gcf[rs] = (getc[bS + gi] > 0.5f) && h0;
        const float* xr = &x[(bS + gi) * DIMC + IOS];
        tgt[rs] = xr[0] + 1.0f + xr[1];
    }

    const int njt = h0 ? (SLEN / 64) : (it + 1);
    for (int jt = 0; jt < njt; jt++) {
        const int j0 = jt * 64;
        __syncthreads();   // previous tile's sK/sV reads complete
        #pragma unroll
        for (int i = 0; i < 8; i++) {
            const int id = tid + 128 * i;
            const int row = id >> 4, col = (id & 15) * 4;
            const size_t goff = (bS + j0 + row) * DIMC + h * HDIM + col;
            cpa16(sKa + (row * AS + col) * 4, &k[goff]);
            cpa16(sVa + (row * AS + col) * 4, &v[goff]);
        }
        asm volatile("cp.async.commit_group;\ncp.async.wait_group 0;" ::: "memory");
        __syncthreads();

        // GEMM1: S = Q @ K^T  (B(k=d,n=j) = K[j][d])
        float s[8][4];
        #pragma unroll
        for (int na = 0; na < 8; na++)
            #pragma unroll
            for (int j = 0; j < 4; j++) s[na][j] = 0.f;
        #pragma unroll
        for (int k8 = 0; k8 < 8; k8++) {
            #pragma unroll
            for (int na = 0; na < 8; na++) {
                uint32_t bf[2];
                const int nb = (na * 8 + g) * AS + k8 * 8 + tg;
                bf[0] = sK[nb]; bf[1] = sK[nb + 4];
                mma8(s[na], afq[k8], bf);
            }
        }

        // bias + online softmax per row-half
        #pragma unroll
        for (int rs = 0; rs < 2; rs++) {
            const int gi = i0 + w * 16 + g + 8 * rs;
            if (gcf[rs]) {
                #pragma unroll
                for (int na = 0; na < 8; na++)
                    #pragma unroll
                    for (int c = 0; c < 2; c++) {
                        const int gj = j0 + na * 8 + 2 * tg + c;
                        s[na][2 * rs + c] = -slope * fabsf(tgt[rs] - (float)gj);
                    }
            } else {
                #pragma unroll
                for (int na = 0; na < 8; na++)
                    #pragma unroll
                    for (int c = 0; c < 2; c++) {
                        const int gj = j0 + na * 8 + 2 * tg + c;
                        s[na][2 * rs + c] = (gj <= gi)
                            ? s[na][2 * rs + c] - slope * (float)(gi - gj) : -1e30f;
                    }
            }
            float tm = -INFINITY;
            #pragma unroll
            for (int na = 0; na < 8; na++)
                tm = fmaxf(tm, fmaxf(s[na][2 * rs], s[na][2 * rs + 1]));
            tm = fmaxf(tm, __shfl_xor_sync(0xffffffffu, tm, 1));
            tm = fmaxf(tm, __shfl_xor_sync(0xffffffffu, tm, 2));
            const float mn = fmaxf(m2[rs], tm);
            const float alpha = __expf(m2[rs] - mn);
            m2[rs] = mn;
            float rsum = 0.f;
            #pragma unroll
            for (int na = 0; na < 8; na++)
                #pragma unroll
                for (int c = 0; c < 2; c++) {
                    float e = __expf(s[na][2 * rs + c] - mn);
                    s[na][2 * rs + c] = e; rsum += e;
                }
            rsum += __shfl_xor_sync(0xffffffffu, rsum, 1);
            rsum += __shfl_xor_sync(0xffffffffu, rsum, 2);
            l2[rs] = l2[rs] * alpha + rsum;
            #pragma unroll
            for (int na = 0; na < 8; na++) {
                O[na][2 * rs + 0] *= alpha;
                O[na][2 * rs + 1] *= alpha;
            }
        }

        // P -> sP (warp-private rows)
        #pragma unroll
        for (int na = 0; na < 8; na++) {
            const int r = w * 16 + g, c = na * 8 + 2 * tg;
            sQP[r * AS + c]           = f2tf(s[na][0]);
            sQP[r * AS + c + 1]       = f2tf(s[na][1]);
            sQP[(r + 8) * AS + c]     = f2tf(s[na][2]);
            sQP[(r + 8) * AS + c + 1] = f2tf(s[na][3]);
        }
        __syncwarp();

        // GEMM2: O += P @ V  (B(k=j,n=d) = V[j][d], row-major V)
        #pragma unroll
        for (int k8 = 0; k8 < 8; k8++) {
            uint32_t af[4];
            const int rb = (w * 16 + g) * AS + k8 * 8 + tg;
            af[0] = sQP[rb];     af[1] = sQP[rb + 8 * AS];
            af[2] = sQP[rb + 4]; af[3] = sQP[rb + 8 * AS + 4];
            #pragma unroll
            for (int na = 0; na < 8; na++) {
                uint32_t bf[2];
                const int nb = (k8 * 8 + tg) * AS + na * 8 + g;
                bf[0] = sV[nb]; bf[1] = sV[nb + 4 * AS];
                mma8(O[na], af, bf);
            }
        }
    }

    #pragma unroll
    for (int rs = 0; rs < 2; rs++) {
        const float inv = 1.0f / l2[rs];
        const size_t rowoff = (bS + i0 + w * 16 + g + 8 * rs) * DIMC + h * HDIM;
        #pragma unroll
        for (int na = 0; na < 8; na++) {
            *(float2*)&ao[rowoff + na * 8 + 2 * tg] =
                make_float2(O[na][2 * rs] * inv, O[na][2 * rs + 1] * inv);
        }
    }
}

// ============================================================
extern "C" void kernel_launch(void* const* d_in, const int* in_sizes, int n_in,
                              void* d_out, int out_size)
{
    const float* x   = (const float*)d_in[0];
    const float* gch = (const float*)d_in[1];
    const float* pch = (const float*)d_in[2];
    const float* wq  = (const float*)d_in[3];
    const float* wk  = (const float*)d_in[4];
    const float* wv  = (const float*)d_in[5];
    const float* wo  = (const float*)d_in[6];
    float* out = (float*)d_out;

    float *qp, *kp, *vp, *aop;
    cudaGetSymbolAddress((void**)&qp,  g_q);
    cudaGetSymbolAddress((void**)&kp,  g_k);
    cudaGetSymbolAddress((void**)&vp,  g_v);
    cudaGetSymbolAddress((void**)&aop, g_ao);

    gemm_qkv3<<<dim3(DIMC / 128, MROWS / 128, 3), 256>>>(x, wq, wk, wv, qp, kp, vp);

    cudaFuncSetAttribute(attn_mma,
                         cudaFuncAttributeMaxDynamicSharedMemorySize, ATTN_SMEM);
    attn_mma<<<dim3(SLEN / 64, NH, BATCH), 128, ATTN_SMEM>>>(qp, kp, vp, x, gch, aop);

    gemm_out<<<dim3(DIMC / 128, MROWS / 128), 256>>>(aop, wo, out, x, gch, pch);
}

// round 8
// speedup vs baseline: 3.4747x; 1.0771x over previous
#include <cuda_runtime.h>
#include <math.h>
#include <stdint.h>

#define SLEN  2048
#define DIMC  1024
#define NH    16
#define HDIM  64
#define BATCH 2
#define MROWS (BATCH*SLEN)   /* 4096 */
#define IOS   1008           /* DIM - 16 */

// ---- scratch (allocation-free rule: __device__ globals) ----
__device__ float g_q [(size_t)MROWS * DIMC];
__device__ float g_k [(size_t)MROWS * DIMC];
__device__ float g_v [(size_t)MROWS * DIMC];
__device__ float g_ao[(size_t)MROWS * DIMC];

__device__ __forceinline__ uint32_t f2tf(float f) {
    uint32_t u;
    asm("cvt.rna.tf32.f32 %0, %1;" : "=r"(u) : "f"(f));
    return u;
}

// D = A(16x8 tf32, row) * B(8x8 tf32, col) + D (fp32). fp32 operands truncate (RZ).
__device__ __forceinline__ void mma8(float c[4], const uint32_t a[4], const uint32_t b[2]) {
    asm volatile(
        "mma.sync.aligned.m16n8k8.row.col.f32.tf32.tf32.f32 "
        "{%0,%1,%2,%3}, {%4,%5,%6,%7}, {%8,%9}, {%0,%1,%2,%3};"
        : "+f"(c[0]), "+f"(c[1]), "+f"(c[2]), "+f"(c[3])
        : "r"(a[0]), "r"(a[1]), "r"(a[2]), "r"(a[3]), "r"(b[0]), "r"(b[1]));
}

__device__ __forceinline__ void cpa16(uint32_t saddr, const void* gp) {
    asm volatile("cp.async.cg.shared.global [%0], [%1], 16;" :: "r"(saddr), "l"(gp));
}
__device__ __forceinline__ void cp_commit() {
    asm volatile("cp.async.commit_group;" ::: "memory");
}
template<int N> __device__ __forceinline__ void cp_wait() {
    asm volatile("cp.async.wait_group %0;" :: "n"(N) : "memory");
}

// ============================================================
// tf32 GEMM core: C[.,1024] = A[.,1024] @ W (+epilogue).
// 128x128 block tile, 8 warps, warp 64x32, K-step 16,
// 3-stage cp.async pipeline, NO conversions in mainloop.
// ============================================================
#define GAS 20     /* A smem stride (banks 4g+tg conflict-free) */
#define GBS 136    /* B smem stride (banks 8tg+g conflict-free) */
#define GSTG 3
#define A_STG (128 * GAS)
#define B_STG (16 * GBS)

__device__ __forceinline__ void gemm_body(
    const float* __restrict__ A, const float* __restrict__ W,
    float* __restrict__ C, const float* __restrict__ resid,
    const float* __restrict__ getc, const float* __restrict__ putc,
    bool cvt, float scale, uint32_t* sA, uint32_t* sB)
{
    const int tid = threadIdx.x, lane = tid & 31, w = tid >> 5;
    const int g = lane >> 2, tg = lane & 3;
    const int wm = w >> 2, wn = w & 3;
    const int m0 = blockIdx.y * 128, n0 = blockIdx.x * 128;

    const int ar = tid >> 2, ac = (tid & 3) * 4;
    const int br = tid >> 5, bc = (tid & 31) * 4;

    const uint32_t sAa = (uint32_t)__cvta_generic_to_shared(sA);
    const uint32_t sBa = (uint32_t)__cvta_generic_to_shared(sB);

    const float* Ap0 = &A[(size_t)(m0 + ar) * DIMC + ac];
    const float* Ap1 = Ap0 + (size_t)64 * DIMC;
    const float* Bp0 = &W[(size_t)br * DIMC + n0 + bc];
    const float* Bp1 = Bp0 + (size_t)8 * DIMC;
    const uint32_t sA0 = sAa + (ar * GAS + ac) * 4;
    const uint32_t sA1 = sAa + ((ar + 64) * GAS + ac) * 4;
    const uint32_t sB0 = sBa + (br * GBS + bc) * 4;
    const uint32_t sB1 = sBa + ((br + 8) * GBS + bc) * 4;

    float acc[16][4];
    #pragma unroll
    for (int i = 0; i < 16; i++)
        #pragma unroll
        for (int j = 0; j < 4; j++) acc[i][j] = 0.f;

    // prologue: issue stages 0..GSTG-2
    #pragma unroll
    for (int s = 0; s < GSTG - 1; s++) {
        const int k0 = s * 16;
        cpa16(sA0 + s * A_STG * 4, Ap0 + k0);
        cpa16(sA1 + s * A_STG * 4, Ap1 + k0);
        cpa16(sB0 + s * B_STG * 4, Bp0 + (size_t)k0 * DIMC);
        cpa16(sB1 + s * B_STG * 4, Bp1 + (size_t)k0 * DIMC);
        cp_commit();
    }

    const int KT = DIMC / 16;
    for (int kt = 0; kt < KT; kt++) {
        cp_wait<GSTG - 2>();     // oldest (kt) done
        __syncthreads();         // visible to all; slot (kt-1)%GSTG free
        if (kt + GSTG - 1 < KT) {
            const int s = (kt + GSTG - 1) % GSTG;
            const int k0 = (kt + GSTG - 1) * 16;
            cpa16(sA0 + s * A_STG * 4, Ap0 + k0);
            cpa16(sA1 + s * A_STG * 4, Ap1 + k0);
            cpa16(sB0 + s * B_STG * 4, Bp0 + (size_t)k0 * DIMC);
            cpa16(sB1 + s * B_STG * 4, Bp1 + (size_t)k0 * DIMC);
        }
        cp_commit();             // keep group count in lockstep

        const uint32_t* cA = sA + (kt % GSTG) * A_STG;
        const uint32_t* cB = sB + (kt % GSTG) * B_STG;
        #pragma unroll
        for (int ks = 0; ks < 16; ks += 8) {
            uint32_t af[4][4], bf[4][2];
            #pragma unroll
            for (int ma = 0; ma < 4; ma++) {
                const int r = wm * 64 + ma * 16 + g;
                af[ma][0] = cA[r * GAS + ks + tg];
                af[ma][1] = cA[(r + 8) * GAS + ks + tg];
                af[ma][2] = cA[r * GAS + ks + tg + 4];
                af[ma][3] = cA[(r + 8) * GAS + ks + tg + 4];
            }
            #pragma unroll
            for (int na = 0; na < 4; na++) {
                const int c = wn * 32 + na * 8 + g;
                bf[na][0] = cB[(ks + tg) * GBS + c];
                bf[na][1] = cB[(ks + tg + 4) * GBS + c];
            }
            #pragma unroll
            for (int ma = 0; ma < 4; ma++)
                #pragma unroll
                for (int na = 0; na < 4; na++)
                    mma8(acc[ma * 4 + na], af[ma], bf[na]);
        }
    }

    #pragma unroll
    for (int ma = 0; ma < 4; ma++) {
        #pragma unroll
        for (int na = 0; na < 4; na++) {
            const int rbase = m0 + wm * 64 + ma * 16 + g;
            const int cbase = n0 + wn * 32 + na * 8 + 2 * tg;
            #pragma unroll
            for (int half = 0; half < 2; half++) {
                const int m = rbase + 8 * half;
                float v0 = acc[ma * 4 + na][2 * half + 0];
                float v1 = acc[ma * 4 + na][2 * half + 1];
                if (cvt) {
                    v0 = __uint_as_float(f2tf(v0 * scale));
                    v1 = __uint_as_float(f2tf(v1 * scale));
                } else if (resid) {
                    v0 += resid[(size_t)m * DIMC + cbase];
                    v1 += resid[(size_t)m * DIMC + cbase + 1];
                    #pragma unroll
                    for (int c = 0; c < 2; c++) {
                        const int n = cbase + c;
                        float* pv = c ? &v1 : &v0;
                        if (n == IOS + 1)  *pv += getc[m];
                        if (n == IOS + 3)  *pv += putc[m];
                        if (n == IOS + 13) *pv  = putc[m];
                    }
                }
                *(float2*)&C[(size_t)m * DIMC + cbase] = make_float2(v0, v1);
            }
        }
    }
}

__global__ __launch_bounds__(256, 2) void gemm_qkv3(
    const float* __restrict__ x,
    const float* __restrict__ wq, const float* __restrict__ wk, const float* __restrict__ wv,
    float* __restrict__ q, float* __restrict__ k, float* __restrict__ v)
{
    __shared__ uint32_t sA[GSTG * A_STG];
    __shared__ uint32_t sB[GSTG * B_STG];
    const int z = blockIdx.z;
    const float* W = (z == 0) ? wq : (z == 1) ? wk : wv;
    float* C = (z == 0) ? q : (z == 1) ? k : v;
    const float scale = (z == 0) ? 0.125f : 1.0f;
    gemm_body(x, W, C, nullptr, nullptr, nullptr, true, scale, sA, sB);
}

__global__ __launch_bounds__(256, 2) void gemm_out(
    const float* __restrict__ A, const float* __restrict__ W,
    float* __restrict__ C, const float* __restrict__ resid,
    const float* __restrict__ getc, const float* __restrict__ putc)
{
    __shared__ uint32_t sA[GSTG * A_STG];
    __shared__ uint32_t sB[GSTG * B_STG];
    gemm_body(A, W, C, resid, getc, putc, false, 1.0f, sA, sB);
}

// ============================================================
// Flash attention, tf32 mma, software-pipelined:
// double-buffered K (next-K loads during softmax+PV),
// V load overlaps GEMM1. 128 thr / 4 warps, warp = 16 q-rows.
// ============================================================
#define AS 68
#define ATTN_SMEM (4 * 64 * AS * 4)   /* sK[2] + sV + sQP = 69.6 KB */

__global__ __launch_bounds__(128, 3) void attn_mma(
    const float* __restrict__ q, const float* __restrict__ k,
    const float* __restrict__ v, const float* __restrict__ x,
    const float* __restrict__ getc, float* __restrict__ ao)
{
    extern __shared__ uint32_t smem[];
    uint32_t* sK  = smem;               // 2 buffers
    uint32_t* sV  = sK + 2 * 64 * AS;
    uint32_t* sQP = sV + 64 * AS;

    const uint32_t sKa  = (uint32_t)__cvta_generic_to_shared(sK);
    const uint32_t sVa  = (uint32_t)__cvta_generic_to_shared(sV);
    const uint32_t sQPa = (uint32_t)__cvta_generic_to_shared(sQP);

    const int tid = threadIdx.x, lane = tid & 31, w = tid >> 5;
    const int g = lane >> 2, tg = lane & 3;
    const int it = gridDim.x - 1 - blockIdx.x;   // heavy blocks first
    const int h = blockIdx.y, b = blockIdx.z;
    const int i0 = it * 64;
    const size_t bS = (size_t)b * SLEN;

    // per-thread tile slots
    int lrow[8], lcol[8];
    #pragma unroll
    for (int i = 0; i < 8; i++) {
        const int id = tid + 128 * i;
        lrow[i] = id >> 4; lcol[i] = (id & 15) * 4;
    }

    // stage Q tile (tf32-rounded, pre-scaled) and hoist fragments
    #pragma unroll
    for (int i = 0; i < 8; i++)
        cpa16(sQPa + (lrow[i] * AS + lcol[i]) * 4,
              &q[(bS + i0 + lrow[i]) * DIMC + h * HDIM + lcol[i]]);
    cp_commit(); cp_wait<0>();
    __syncthreads();
    uint32_t afq[8][4];
    #pragma unroll
    for (int k8 = 0; k8 < 8; k8++) {
        const int rb = (w * 16 + g) * AS + k8 * 8 + tg;
        afq[k8][0] = sQP[rb];     afq[k8][1] = sQP[rb + 8 * AS];
        afq[k8][2] = sQP[rb + 4]; afq[k8][3] = sQP[rb + 8 * AS + 4];
    }
    __syncthreads();   // sQP now free for P

    const float slope = exp2f(-0.5f * (float)(h + 1));
    const bool h0 = (h == 0);

    float m2[2] = {-INFINITY, -INFINITY}, l2[2] = {0.f, 0.f};
    float O[8][4];
    #pragma unroll
    for (int na = 0; na < 8; na++)
        #pragma unroll
        for (int j = 0; j < 4; j++) O[na][j] = 0.f;

    bool gcf[2]; float tgt[2];
    #pragma unroll
    for (int rs = 0; rs < 2; rs++) {
        const int gi = i0 + w * 16 + g + 8 * rs;
        gcf[rs] = (getc[bS + gi] > 0.5f) && h0;
        const float* xr = &x[(bS + gi) * DIMC + IOS];
        tgt[rs] = xr[0] + 1.0f + xr[1];
    }

    const int njt = h0 ? (SLEN / 64) : (it + 1);

    // prologue: K[0] -> sK buf 0
    #pragma unroll
    for (int i = 0; i < 8; i++)
        cpa16(sKa + (lrow[i] * AS + lcol[i]) * 4,
              &k[(bS + lrow[i]) * DIMC + h * HDIM + lcol[i]]);
    cp_commit();                                  // pending: [K0]

    for (int jt = 0; jt < njt; jt++) {
        const int j0 = jt * 64;
        const int buf = jt & 1;
        __syncthreads();   // prev GEMM2 (sV) and prev GEMM1 (sK[buf^1]) done

        // V[jt] load overlaps GEMM1
        #pragma unroll
        for (int i = 0; i < 8; i++)
            cpa16(sVa + (lrow[i] * AS + lcol[i]) * 4,
                  &v[(bS + j0 + lrow[i]) * DIMC + h * HDIM + lcol[i]]);
        cp_commit();                              // pending: [K_jt, V_jt]
        cp_wait<1>();                             // K_jt done
        __syncthreads();

        // GEMM1: S = Q @ K^T
        const uint32_t* cK = sK + buf * 64 * AS;
        float s[8][4];
        #pragma unroll
        for (int na = 0; na < 8; na++)
            #pragma unroll
            for (int j = 0; j < 4; j++) s[na][j] = 0.f;
        #pragma unroll
        for (int k8 = 0; k8 < 8; k8++) {
            #pragma unroll
            for (int na = 0; na < 8; na++) {
                uint32_t bf[2];
                const int nb = (na * 8 + g) * AS + k8 * 8 + tg;
                bf[0] = cK[nb]; bf[1] = cK[nb + 4];
                mma8(s[na], afq[k8], bf);
            }
        }

        // prefetch next K during softmax + GEMM2
        if (jt + 1 < njt) {
            const int nj0 = (jt + 1) * 64;
            const uint32_t kb = sKa + (buf ^ 1) * 64 * AS * 4;
            #pragma unroll
            for (int i = 0; i < 8; i++)
                cpa16(kb + (lrow[i] * AS + lcol[i]) * 4,
                      &k[(bS + nj0 + lrow[i]) * DIMC + h * HDIM + lcol[i]]);
        }
        cp_commit();                              // pending: [V_jt, K_next]

        // bias + online softmax per row-half
        #pragma unroll
        for (int rs = 0; rs < 2; rs++) {
            const int gi = i0 + w * 16 + g + 8 * rs;
            if (gcf[rs]) {
                #pragma unroll
                for (int na = 0; na < 8; na++)
                    #pragma unroll
                    for (int c = 0; c < 2; c++) {
                        const int gj = j0 + na * 8 + 2 * tg + c;
                        s[na][2 * rs + c] = -slope * fabsf(tgt[rs] - (float)gj);
                    }
            } else {
                #pragma unroll
                for (int na = 0; na < 8; na++)
                    #pragma unroll
                    for (int c = 0; c < 2; c++) {
                        const int gj = j0 + na * 8 + 2 * tg + c;
                        s[na][2 * rs + c] = (gj <= gi)
                            ? s[na][2 * rs + c] - slope * (float)(gi - gj) : -1e30f;
                    }
            }
            float tm = -INFINITY;
            #pragma unroll
            for (int na = 0; na < 8; na++)
                tm = fmaxf(tm, fmaxf(s[na][2 * rs], s[na][2 * rs + 1]));
            tm = fmaxf(tm, __shfl_xor_sync(0xffffffffu, tm, 1));
            tm = fmaxf(tm, __shfl_xor_sync(0xffffffffu, tm, 2));
            const float mn = fmaxf(m2[rs], tm);
            const float alpha = __expf(m2[rs] - mn);
            m2[rs] = mn;
            float rsum = 0.f;
            #pragma unroll
            for (int na = 0; na < 8; na++)
                #pragma unroll
                for (int c = 0; c < 2; c++) {
                    float e = __expf(s[na][2 * rs + c] - mn);
                    s[na][2 * rs + c] = e; rsum += e;
                }
            rsum += __shfl_xor_sync(0xffffffffu, rsum, 1);
            rsum += __shfl_xor_sync(0xffffffffu, rsum, 2);
            l2[rs] = l2[rs] * alpha + rsum;
            #pragma unroll
            for (int na = 0; na < 8; na++) {
                O[na][2 * rs + 0] *= alpha;
                O[na][2 * rs + 1] *= alpha;
            }
        }

        cp_wait<1>();       // V_jt done (K_next may pend)
        __syncthreads();

        // P -> sP (warp-private rows), raw fp32 bits (mma truncates)
        #pragma unroll
        for (int na = 0; na < 8; na++) {
            const int r = w * 16 + g, c = na * 8 + 2 * tg;
            sQP[r * AS + c]           = __float_as_uint(s[na][0]);
            sQP[r * AS + c + 1]       = __float_as_uint(s[na][1]);
            sQP[(r + 8) * AS + c]     = __float_as_uint(s[na][2]);
            sQP[(r + 8) * AS + c + 1] = __float_as_uint(s[na][3]);
        }
        __syncwarp();

        // GEMM2: O += P @ V (row-major V as B)
        #pragma unroll
        for (int k8 = 0; k8 < 8; k8++) {
            uint32_t af[4];
            const int rb = (w * 16 + g) * AS + k8 * 8 + tg;
            af[0] = sQP[rb];     af[1] = sQP[rb + 8 * AS];
            af[2] = sQP[rb + 4]; af[3] = sQP[rb + 8 * AS + 4];
            #pragma unroll
            for (int na = 0; na < 8; na++) {
                uint32_t bf[2];
                const int nb = (k8 * 8 + tg) * AS + na * 8 + g;
                bf[0] = sV[nb]; bf[1] = sV[nb + 4 * AS];
                mma8(O[na], af, bf);
            }
        }
    }

    #pragma unroll
    for (int rs = 0; rs < 2; rs++) {
        const float inv = 1.0f / l2[rs];
        const size_t rowoff = (bS + i0 + w * 16 + g + 8 * rs) * DIMC + h * HDIM;
        #pragma unroll
        for (int na = 0; na < 8; na++) {
            *(float2*)&ao[rowoff + na * 8 + 2 * tg] =
                make_float2(O[na][2 * rs] * inv, O[na][2 * rs + 1] * inv);
        }
    }
}

// ============================================================
extern "C" void kernel_launch(void* const* d_in, const int* in_sizes, int n_in,
                              void* d_out, int out_size)
{
    const float* x   = (const float*)d_in[0];
    const float* gch = (const float*)d_in[1];
    const float* pch = (const float*)d_in[2];
    const float* wq  = (const float*)d_in[3];
    const float* wk  = (const float*)d_in[4];
    const float* wv  = (const float*)d_in[5];
    const float* wo  = (const float*)d_in[6];
    float* out = (float*)d_out;

    float *qp, *kp, *vp, *aop;
    cudaGetSymbolAddress((void**)&qp,  g_q);
    cudaGetSymbolAddress((void**)&kp,  g_k);
    cudaGetSymbolAddress((void**)&vp,  g_v);
    cudaGetSymbolAddress((void**)&aop, g_ao);

    gemm_qkv3<<<dim3(DIMC / 128, MROWS / 128, 3), 256>>>(x, wq, wk, wv, qp, kp, vp);

    cudaFuncSetAttribute(attn_mma,
                         cudaFuncAttributeMaxDynamicSharedMemorySize, ATTN_SMEM);
    attn_mma<<<dim3(SLEN / 64, NH, BATCH), 128, ATTN_SMEM>>>(qp, kp, vp, x, gch, aop);

    gemm_out<<<dim3(DIMC / 128, MROWS / 128), 256>>>(aop, wo, out, x, gch, pch);
}

// round 10
// speedup vs baseline: 3.5413x; 1.0192x over previous
#include <cuda_runtime.h>
#include <math.h>
#include <stdint.h>

#define SLEN  2048
#define DIMC  1024
#define NH    16
#define HDIM  64
#define BATCH 2
#define MROWS (BATCH*SLEN)   /* 4096 */
#define IOS   1008           /* DIM - 16 */

// ---- scratch (allocation-free rule: __device__ globals) ----
__device__ float g_q [(size_t)MROWS * DIMC];
__device__ float g_k [(size_t)MROWS * DIMC];
__device__ float g_v [(size_t)MROWS * DIMC];
__device__ float g_ao[(size_t)MROWS * DIMC];
__device__ float g_wt[(size_t)4 * DIMC * DIMC];   // transposed weights

__device__ __forceinline__ uint32_t f2tf(float f) {
    uint32_t u;
    asm("cvt.rna.tf32.f32 %0, %1;" : "=r"(u) : "f"(f));
    return u;
}

// D = A(16x8 tf32, row) * B(8x8 tf32, col) + D (fp32). fp32 operands truncate (RZ).
__device__ __forceinline__ void mma8(float c[4], const uint32_t a[4], const uint32_t b[2]) {
    asm volatile(
        "mma.sync.aligned.m16n8k8.row.col.f32.tf32.tf32.f32 "
        "{%0,%1,%2,%3}, {%4,%5,%6,%7}, {%8,%9}, {%0,%1,%2,%3};"
        : "+f"(c[0]), "+f"(c[1]), "+f"(c[2]), "+f"(c[3])
        : "r"(a[0]), "r"(a[1]), "r"(a[2]), "r"(a[3]), "r"(b[0]), "r"(b[1]));
}

__device__ __forceinline__ void ldsm4(uint32_t r[4], uint32_t saddr) {
    asm volatile("ldmatrix.sync.aligned.m8n8.x4.shared.b16 {%0,%1,%2,%3}, [%4];"
        : "=r"(r[0]), "=r"(r[1]), "=r"(r[2]), "=r"(r[3]) : "r"(saddr));
}

__device__ __forceinline__ void cpa16(uint32_t saddr, const void* gp) {
    asm volatile("cp.async.cg.shared.global [%0], [%1], 16;" :: "r"(saddr), "l"(gp));
}
__device__ __forceinline__ void cp_commit() {
    asm volatile("cp.async.commit_group;" ::: "memory");
}
template<int N> __device__ __forceinline__ void cp_wait() {
    asm volatile("cp.async.wait_group %0;" :: "n"(N) : "memory");
}

// ============================================================
// Weight transpose: g_wt[z] = W_z^T (k-contiguous rows).
// ============================================================
__global__ __launch_bounds__(256) void transpose_w(
    const float* __restrict__ w0, const float* __restrict__ w1,
    const float* __restrict__ w2, const float* __restrict__ w3,
    float* __restrict__ wt)
{
    __shared__ float t[32][33];
    const float* W = (blockIdx.z == 0) ? w0 : (blockIdx.z == 1) ? w1
                   : (blockIdx.z == 2) ? w2 : w3;
    float* WT = wt + (size_t)blockIdx.z * DIMC * DIMC;
    const int x0 = blockIdx.x * 32, y0 = blockIdx.y * 32;
    #pragma unroll
    for (int i = threadIdx.y; i < 32; i += 8)
        t[i][threadIdx.x] = W[(size_t)(y0 + i) * DIMC + x0 + threadIdx.x];
    __syncthreads();
    #pragma unroll
    for (int i = threadIdx.y; i < 32; i += 8)
        WT[(size_t)(x0 + i) * DIMC + y0 + threadIdx.x] = t[threadIdx.x][i];
}

// ============================================================
// tf32 GEMM (NT): C[.,1024] = A[.,1024] @ BT^T, both operands
// k-contiguous. 128x128 block tile, 8 warps, warp 64x32,
// K-step 16, 3-stage cp.async, ldmatrix fragment loads.
// ============================================================
#define GS 20              /* smem row stride (words); 20r mod 32 spans all banks */
#define TSTG (128 * GS)    /* words per tile stage */
#define GSTG 3

__device__ __forceinline__ void gemm_body(
    const float* __restrict__ A, const float* __restrict__ BT,
    float* __restrict__ C, const float* __restrict__ resid,
    const float* __restrict__ getc, const float* __restrict__ putc,
    bool cvt, float scale, uint32_t* sA, uint32_t* sB)
{
    const int tid = threadIdx.x, lane = tid & 31, w = tid >> 5;
    const int g = lane >> 2, tg = lane & 3;
    const int wm = w >> 2, wn = w & 3;
    const int m0 = blockIdx.y * 128, n0 = blockIdx.x * 128;

    const int r0 = tid >> 2, kc = (tid & 3) * 4;

    const uint32_t sAa = (uint32_t)__cvta_generic_to_shared(sA);
    const uint32_t sBa = (uint32_t)__cvta_generic_to_shared(sB);

    const float* Ap0 = &A [(size_t)(m0 + r0) * DIMC + kc];
    const float* Ap1 = Ap0 + (size_t)64 * DIMC;
    const float* Bp0 = &BT[(size_t)(n0 + r0) * DIMC + kc];
    const float* Bp1 = Bp0 + (size_t)64 * DIMC;
    const uint32_t dA0 = sAa + (r0 * GS + kc) * 4;
    const uint32_t dA1 = sAa + ((r0 + 64) * GS + kc) * 4;
    const uint32_t dB0 = sBa + (r0 * GS + kc) * 4;
    const uint32_t dB1 = sBa + ((r0 + 64) * GS + kc) * 4;

    // per-lane ldmatrix address components
    const uint32_t aLane = ((wm * 64 + (lane & 15)) * GS + ((lane >> 4) & 1) * 4) * 4;
    const uint32_t bLane = ((wn * 32 + (lane & 7) + ((lane >> 4) & 1) * 8) * GS
                            + ((lane >> 3) & 1) * 4) * 4;

    float acc[16][4];
    #pragma unroll
    for (int i = 0; i < 16; i++)
        #pragma unroll
        for (int j = 0; j < 4; j++) acc[i][j] = 0.f;

    #pragma unroll
    for (int s = 0; s < GSTG - 1; s++) {
        const int k0 = s * 16;
        cpa16(dA0 + s * TSTG * 4, Ap0 + k0);
        cpa16(dA1 + s * TSTG * 4, Ap1 + k0);
        cpa16(dB0 + s * TSTG * 4, Bp0 + k0);
        cpa16(dB1 + s * TSTG * 4, Bp1 + k0);
        cp_commit();
    }

    const int KT = DIMC / 16;
    for (int kt = 0; kt < KT; kt++) {
        cp_wait<GSTG - 2>();
        __syncthreads();
        if (kt + GSTG - 1 < KT) {
            const int s = (kt + GSTG - 1) % GSTG;
            const int k0 = (kt + GSTG - 1) * 16;
            cpa16(dA0 + s * TSTG * 4, Ap0 + k0);
            cpa16(dA1 + s * TSTG * 4, Ap1 + k0);
            cpa16(dB0 + s * TSTG * 4, Bp0 + k0);
            cpa16(dB1 + s * TSTG * 4, Bp1 + k0);
        }
        cp_commit();

        const uint32_t aBase = sAa + (kt % GSTG) * TSTG * 4 + aLane;
        const uint32_t bBase = sBa + (kt % GSTG) * TSTG * 4 + bLane;
        #pragma unroll
        for (int ks = 0; ks < 16; ks += 8) {
            uint32_t af[4][4], bf[2][4];
            #pragma unroll
            for (int ma = 0; ma < 4; ma++)
                ldsm4(af[ma], aBase + (ma * 16 * GS + ks) * 4);
            #pragma unroll
            for (int n2 = 0; n2 < 2; n2++)
                ldsm4(bf[n2], bBase + (n2 * 16 * GS + ks) * 4);
            #pragma unroll
            for (int ma = 0; ma < 4; ma++)
                #pragma unroll
                for (int na = 0; na < 4; na++)
                    mma8(acc[ma * 4 + na], af[ma], &bf[na >> 1][(na & 1) * 2]);
        }
    }

    #pragma unroll
    for (int ma = 0; ma < 4; ma++) {
        #pragma unroll
        for (int na = 0; na < 4; na++) {
            const int rbase = m0 + wm * 64 + ma * 16 + g;
            const int cbase = n0 + wn * 32 + na * 8 + 2 * tg;
            #pragma unroll
            for (int half = 0; half < 2; half++) {
                const int m = rbase + 8 * half;
                float v0 = acc[ma * 4 + na][2 * half + 0];
                float v1 = acc[ma * 4 + na][2 * half + 1];
                if (cvt) {
                    v0 = __uint_as_float(f2tf(v0 * scale));
                    v1 = __uint_as_float(f2tf(v1 * scale));
                } else if (resid) {
                    v0 += resid[(size_t)m * DIMC + cbase];
                    v1 += resid[(size_t)m * DIMC + cbase + 1];
                    #pragma unroll
                    for (int c = 0; c < 2; c++) {
                        const int n = cbase + c;
                        float* pv = c ? &v1 : &v0;
                        if (n == IOS + 1)  *pv += getc[m];
                        if (n == IOS + 3)  *pv += putc[m];
                        if (n == IOS + 13) *pv  = putc[m];
                    }
                }
                *(float2*)&C[(size_t)m * DIMC + cbase] = make_float2(v0, v1);
            }
        }
    }
}

__global__ __launch_bounds__(256, 2) void gemm_qkv3(
    const float* __restrict__ x, const float* __restrict__ wt,
    float* __restrict__ q, float* __restrict__ k, float* __restrict__ v)
{
    __shared__ uint32_t sA[GSTG * TSTG];
    __shared__ uint32_t sB[GSTG * TSTG];
    const int z = blockIdx.z;
    const float* BT = wt + (size_t)z * DIMC * DIMC;
    float* C = (z == 0) ? q : (z == 1) ? k : v;
    const float scale = (z == 0) ? 0.125f : 1.0f;
    gemm_body(x, BT, C, nullptr, nullptr, nullptr, true, scale, sA, sB);
}

__global__ __launch_bounds__(256, 2) void gemm_out(
    const float* __restrict__ A, const float* __restrict__ wt,
    float* __restrict__ C, const float* __restrict__ resid,
    const float* __restrict__ getc, const float* __restrict__ putc)
{
    __shared__ uint32_t sA[GSTG * TSTG];
    __shared__ uint32_t sB[GSTG * TSTG];
    gemm_body(A, wt + (size_t)3 * DIMC * DIMC, C, resid, getc, putc, false, 1.0f, sA, sB);
}

// ============================================================
// Flash attention, tf32 mma, pipelined; ldmatrix for K (GEMM1 B)
// and P (GEMM2 A) fragments. 128 thr / 4 warps, warp = 16 q-rows.
// ============================================================
#define AS 68
#define ATTN_SMEM (4 * 64 * AS * 4)   /* sK[2] + sV + sQP */

__global__ __launch_bounds__(128, 3) void attn_mma(
    const float* __restrict__ q, const float* __restrict__ k,
    const float* __restrict__ v, const float* __restrict__ x,
    const float* __restrict__ getc, float* __restrict__ ao)
{
    extern __shared__ uint32_t smem[];
    uint32_t* sK  = smem;               // 2 buffers
    uint32_t* sV  = sK + 2 * 64 * AS;
    uint32_t* sQP = sV + 64 * AS;

    const uint32_t sKa  = (uint32_t)__cvta_generic_to_shared(sK);
    const uint32_t sVa  = (uint32_t)__cvta_generic_to_shared(sV);
    const uint32_t sQPa = (uint32_t)__cvta_generic_to_shared(sQP);

    const int tid = threadIdx.x, lane = tid & 31, w = tid >> 5;
    const int g = lane >> 2, tg = lane & 3;
    const int it = gridDim.x - 1 - blockIdx.x;   // heavy blocks first
    const int h = blockIdx.y, b = blockIdx.z;
    const int i0 = it * 64;
    const size_t bS = (size_t)b * SLEN;

    // ldmatrix lane address components (stride AS, conflict-free: 68 mod 32 = 4)
    const uint32_t kLane = (((lane & 7) + ((lane >> 4) & 1) * 8) * AS
                            + ((lane >> 3) & 1) * 4) * 4;
    const uint32_t pLane = ((w * 16 + (lane & 15)) * AS + ((lane >> 4) & 1) * 4) * 4;

    int lrow[8], lcol[8];
    #pragma unroll
    for (int i = 0; i < 8; i++) {
        const int id = tid + 128 * i;
        lrow[i] = id >> 4; lcol[i] = (id & 15) * 4;
    }

    // stage Q tile (tf32-rounded, pre-scaled) and hoist fragments
    #pragma unroll
    for (int i = 0; i < 8; i++)
        cpa16(sQPa + (lrow[i] * AS + lcol[i]) * 4,
              &q[(bS + i0 + lrow[i]) * DIMC + h * HDIM + lcol[i]]);
    cp_commit(); cp_wait<0>();
    __syncthreads();
    uint32_t afq[8][4];
    #pragma unroll
    for (int k8 = 0; k8 < 8; k8++)
        ldsm4(afq[k8], sQPa + pLane + k8 * 8 * 4);
    __syncthreads();   // sQP now free for P

    const float slope = exp2f(-0.5f * (float)(h + 1));
    const bool h0 = (h == 0);

    float m2[2] = {-INFINITY, -INFINITY}, l2[2] = {0.f, 0.f};
    float O[8][4];
    #pragma unroll
    for (int na = 0; na < 8; na++)
        #pragma unroll
        for (int j = 0; j < 4; j++) O[na][j] = 0.f;

    bool gcf[2]; float tgt[2];
    #pragma unroll
    for (int rs = 0; rs < 2; rs++) {
        const int gi = i0 + w * 16 + g + 8 * rs;
        gcf[rs] = (getc[bS + gi] > 0.5f) && h0;
        const float* xr = &x[(bS + gi) * DIMC + IOS];
        tgt[rs] = xr[0] + 1.0f + xr[1];
    }

    const int njt = h0 ? (SLEN / 64) : (it + 1);

    // prologue: K[0] -> sK buf 0
    #pragma unroll
    for (int i = 0; i < 8; i++)
        cpa16(sKa + (lrow[i] * AS + lcol[i]) * 4,
              &k[(bS + lrow[i]) * DIMC + h * HDIM + lcol[i]]);
    cp_commit();

    for (int jt = 0; jt < njt; jt++) {
        const int j0 = jt * 64;
        const int buf = jt & 1;
        __syncthreads();

        // V[jt] load overlaps GEMM1
        #pragma unroll
        for (int i = 0; i < 8; i++)
            cpa16(sVa + (lrow[i] * AS + lcol[i]) * 4,
                  &v[(bS + j0 + lrow[i]) * DIMC + h * HDIM + lcol[i]]);
        cp_commit();
        cp_wait<1>();
        __syncthreads();

        // GEMM1: S = Q @ K^T (K frags via ldmatrix)
        const uint32_t kBase = sKa + buf * 64 * AS * 4 + kLane;
        float s[8][4];
        #pragma unroll
        for (int na = 0; na < 8; na++)
            #pragma unroll
            for (int j = 0; j < 4; j++) s[na][j] = 0.f;
        #pragma unroll
        for (int k8 = 0; k8 < 8; k8++) {
            uint32_t bf[4][4];
            #pragma unroll
            for (int n2 = 0; n2 < 4; n2++)
                ldsm4(bf[n2], kBase + (n2 * 16 * AS + k8 * 8) * 4);
            #pragma unroll
            for (int na = 0; na < 8; na++)
                mma8(s[na], afq[k8], &bf[na >> 1][(na & 1) * 2]);
        }

        // prefetch next K during softmax + GEMM2
        if (jt + 1 < njt) {
            const int nj0 = (jt + 1) * 64;
            const uint32_t kb = sKa + (buf ^ 1) * 64 * AS * 4;
            #pragma unroll
            for (int i = 0; i < 8; i++)
                cpa16(kb + (lrow[i] * AS + lcol[i]) * 4,
                      &k[(bS + nj0 + lrow[i]) * DIMC + h * HDIM + lcol[i]]);
        }
        cp_commit();

        // bias + online softmax per row-half
        #pragma unroll
        for (int rs = 0; rs < 2; rs++) {
            const int gi = i0 + w * 16 + g + 8 * rs;
            if (gcf[rs]) {
                #pragma unroll
                for (int na = 0; na < 8; na++)
                    #pragma unroll
                    for (int c = 0; c < 2; c++) {
                        const int gj = j0 + na * 8 + 2 * tg + c;
                        s[na][2 * rs + c] = -slope * fabsf(tgt[rs] - (float)gj);
                    }
            } else {
                #pragma unroll
                for (int na = 0; na < 8; na++)
                    #pragma unroll
                    for (int c = 0; c < 2; c++) {
                        const int gj = j0 + na * 8 + 2 * tg + c;
                        s[na][2 * rs + c] = (gj <= gi)
                            ? s[na][2 * rs + c] - slope * (float)(gi - gj) : -1e30f;
                    }
            }
            float tm = -INFINITY;
            #pragma unroll
            for (int na = 0; na < 8; na++)
                tm = fmaxf(tm, fmaxf(s[na][2 * rs], s[na][2 * rs + 1]));
            tm = fmaxf(tm, __shfl_xor_sync(0xffffffffu, tm, 1));
            tm = fmaxf(tm, __shfl_xor_sync(0xffffffffu, tm, 2));
            const float mn = fmaxf(m2[rs], tm);
            const float alpha = __expf(m2[rs] - mn);
            m2[rs] = mn;
            float rsum = 0.f;
            #pragma unroll
            for (int na = 0; na < 8; na++)
                #pragma unroll
                for (int c = 0; c < 2; c++) {
                    float e = __expf(s[na][2 * rs + c] - mn);
                    s[na][2 * rs + c] = e; rsum += e;
                }
            rsum += __shfl_xor_sync(0xffffffffu, rsum, 1);
            rsum += __shfl_xor_sync(0xffffffffu, rsum, 2);
            l2[rs] = l2[rs] * alpha + rsum;
            #pragma unroll
            for (int na = 0; na < 8; na++) {
                O[na][2 * rs + 0] *= alpha;
                O[na][2 * rs + 1] *= alpha;
            }
        }

        cp_wait<1>();       // V_jt done (K_next may pend)
        __syncthreads();

        // P -> sP (warp-private rows), raw fp32 bits (mma truncates)
        #pragma unroll
        for (int na = 0; na < 8; na++) {
            const int r = w * 16 + g, c = na * 8 + 2 * tg;
            sQP[r * AS + c]           = __float_as_uint(s[na][0]);
            sQP[r * AS + c + 1]       = __float_as_uint(s[na][1]);
            sQP[(r + 8) * AS + c]     = __float_as_uint(s[na][2]);
            sQP[(r + 8) * AS + c + 1] = __float_as_uint(s[na][3]);
        }
        __syncwarp();

        // GEMM2: O += P @ V (P frags via ldmatrix; V row-major scalar B)
        #pragma unroll
        for (int k8 = 0; k8 < 8; k8++) {
            uint32_t af[4];
            ldsm4(af, sQPa + pLane + k8 * 8 * 4);
            #pragma unroll
            for (int na = 0; na < 8; na++) {
                uint32_t bf[2];
                const int nb = (k8 * 8 + tg) * AS + na * 8 + g;
                bf[0] = sV[nb]; bf[1] = sV[nb + 4 * AS];
                mma8(O[na], af, bf);
            }
        }
    }

    #pragma unroll
    for (int rs = 0; rs < 2; rs++) {
        const float inv = 1.0f / l2[rs];
        const size_t rowoff = (bS + i0 + w * 16 + g + 8 * rs) * DIMC + h * HDIM;
        #pragma unroll
        for (int na = 0; na < 8; na++) {
            *(float2*)&ao[rowoff + na * 8 + 2 * tg] =
                make_float2(O[na][2 * rs] * inv, O[na][2 * rs + 1] * inv);
        }
    }
}

// ============================================================
extern "C" void kernel_launch(void* const* d_in, const int* in_sizes, int n_in,
                              void* d_out, int out_size)
{
    const float* x   = (const float*)d_in[0];
    const float* gch = (const float*)d_in[1];
    const float* pch = (const float*)d_in[2];
    const float* wq  = (const float*)d_in[3];
    const float* wk  = (const float*)d_in[4];
    const float* wv  = (const float*)d_in[5];
    const float* wo  = (const float*)d_in[6];
    float* out = (float*)d_out;

    float *qp, *kp, *vp, *aop, *wtp;
    cudaGetSymbolAddress((void**)&qp,  g_q);
    cudaGetSymbolAddress((void**)&kp,  g_k);
    cudaGetSymbolAddress((void**)&vp,  g_v);
    cudaGetSymbolAddress((void**)&aop, g_ao);
    cudaGetSymbolAddress((void**)&wtp, g_wt);

    transpose_w<<<dim3(DIMC / 32, DIMC / 32, 4), dim3(32, 8)>>>(wq, wk, wv, wo, wtp);

    gemm_qkv3<<<dim3(DIMC / 128, MROWS / 128, 3), 256>>>(x, wtp, qp, kp, vp);

    cudaFuncSetAttribute(attn_mma,
                         cudaFuncAttributeMaxDynamicSharedMemorySize, ATTN_SMEM);
    attn_mma<<<dim3(SLEN / 64, NH, BATCH), 128, ATTN_SMEM>>>(qp, kp, vp, x, gch, aop);

    gemm_out<<<dim3(DIMC / 128, MROWS / 128), 256>>>(aop, wtp, out, x, gch, pch);
}